// round 2
// baseline (speedup 1.0000x reference)
#include <cuda_runtime.h>

#define NT 5
#define A_FIX 128

__device__ __forceinline__ float fast_rsq(float x) {
    float r; asm("rsqrt.approx.f32 %0, %1;" : "=f"(r) : "f"(x)); return r;
}
__device__ __forceinline__ float fast_ex2(float x) {
    float r; asm("ex2.approx.f32 %0, %1;" : "=f"(r) : "f"(x)); return r;
}
__device__ __forceinline__ float fast_rcp(float x) {
    float r; asm("rcp.approx.f32 %0, %1;" : "=f"(r) : "f"(x)); return r;
}

__global__ __launch_bounds__(256) void gnf_kernel(
    const float* __restrict__ coords,    // [B, A, 3]
    const int*   __restrict__ atom_types,// [B, A]
    const float* __restrict__ query,     // [B, P, 3]
    float*       __restrict__ out,       // [B, P, NT, 3]
    int A, int P)
{
    __shared__ float4 sc[A_FIX];     // coords bucket-sorted by type
    __shared__ int cnt[NT];
    __shared__ int off[NT + 1];

    const int b   = blockIdx.y;
    const int tid = threadIdx.x;

    // ---- per-block preprocessing: bucket atoms by type ----
    if (tid < NT) cnt[tid] = 0;
    __syncthreads();

    int myT = -1, myR = 0;
    if (tid < A) {
        int t = atom_types[b * A + tid];
        if (t >= 0 && t < NT) {
            myT = t;
            myR = atomicAdd(&cnt[t], 1);   // rank within type
        }
    }
    __syncthreads();
    if (tid == 0) {
        int s = 0;
        #pragma unroll
        for (int t = 0; t < NT; t++) { off[t] = s; s += cnt[t]; }
        off[NT] = s;
    }
    __syncthreads();
    if (myT >= 0) {
        const float* c = coords + (b * A + tid) * 3;
        sc[off[myT] + myR] = make_float4(c[0], c[1], c[2], 0.0f);
    }
    __syncthreads();

    // ---- main loop: one query point per thread ----
    const int p = blockIdx.x * blockDim.x + tid;
    if (p >= P) return;

    const float* q = query + ((long)b * P + p) * 3;
    const float qx = q[0], qy = q[1], qz = q[2];

    float* o = out + ((long)b * P + p) * (NT * 3);

    const float NLOG2E = -1.4426950408889634f;  // -log2(e)

    #pragma unroll
    for (int t = 0; t < NT; t++) {
        const int beg = off[t], end = off[t + 1];
        float sw = 0.0f, sx = 0.0f, sy = 0.0f, sz = 0.0f;

        #pragma unroll 4
        for (int a = beg; a < end; a++) {
            float4 c = sc[a];                     // warp-uniform -> LDS broadcast
            float dx = c.x - qx;
            float dy = c.y - qy;
            float dz = c.z - qz;
            float d2 = fmaf(dx, dx, fmaf(dy, dy, dz * dz));
            d2 = fmaxf(d2, 1e-24f);               // avoid 0 * inf
            float dist = d2 * fast_rsq(d2);       // sqrt(d2)
            float e = fast_ex2(dist * NLOG2E);    // exp(-dist)
            sw += e;
            sx = fmaf(e, dx, sx);
            sy = fmaf(e, dy, sy);
            sz = fmaf(e, dz, sz);
        }

        float gx = 0.0f, gy = 0.0f, gz = 0.0f;
        if (end > beg) {
            float inv = fast_rcp(sw);             // softmax normalize
            gx = sx * inv; gy = sy * inv; gz = sz * inv;
            // clip magnitude at 0.3
            float g2 = fmaf(gx, gx, fmaf(gy, gy, gz * gz));
            float f = fminf(1.0f, 0.3f * fast_rsq(fmaxf(g2, 1e-24f)));
            gx *= f; gy *= f; gz *= f;
        }
        o[t * 3 + 0] = gx;
        o[t * 3 + 1] = gy;
        o[t * 3 + 2] = gz;
    }
}

extern "C" void kernel_launch(void* const* d_in, const int* in_sizes, int n_in,
                              void* d_out, int out_size)
{
    const float* coords     = (const float*)d_in[0];  // B*A*3
    const int*   atom_types = (const int*)  d_in[1];  // B*A
    const float* query      = (const float*)d_in[2];  // B*P*3

    const int A = A_FIX;
    const int B = in_sizes[1] / A;
    const int P = in_sizes[2] / (3 * B);

    dim3 grid((P + 255) / 256, B);
    gnf_kernel<<<grid, 256>>>(coords, atom_types, query, (float*)d_out, A, P);
}